// round 10
// baseline (speedup 1.0000x reference)
#include <cuda_runtime.h>

// LSTM_40948218200110: B=4096, T=1024, I=8, H=4 (PyTorch gate order) + FC[H->1].
// R8: 8 lanes per batch element (lane u = p*4+k; p: gate-pair, k: unit), TWO
// independent batch chains per thread (pair-ILP hides the serial-chain latency),
// packed fma.rn.f32x2 dot products (weights SHARED between chains), x staged
// through shared memory (coalesced LDG, broadcast LDS.128 per step).
// Exchange per chain-step: 2 shfl_xor(4) gate swap + 3 shfl_xor(1,2,3) h bcast.
// 512 warps; MIO load ~48 wavefront-cyc/SM/step (3x below R7's binder).

#define T_STEPS 1024
#define I_DIM   8
#define EPB     16            // elements per block (8 groups x 2 chains)
#define BLOCK   64            // threads per block
#define CH_STEPS 8            // timesteps per smem chunk
#define NCHUNK  (T_STEPS / CH_STEPS)   // 128
#define STRIDE4 17            // float4 stride per element in smem (pad 16->17)

typedef unsigned long long ull;

__device__ __forceinline__ float tanh_fast(float x) {
    float y;
    asm("tanh.approx.f32 %0, %1;" : "=f"(y) : "f"(x));
    return y;
}
__device__ __forceinline__ ull ffma2(ull a, ull b, ull c) {
    ull d;
    asm("fma.rn.f32x2 %0, %1, %2, %3;" : "=l"(d) : "l"(a), "l"(b), "l"(c));
    return d;
}
__device__ __forceinline__ ull pack2(float lo, float hi) {
    ull d;
    asm("mov.b64 %0, {%1, %2};" : "=l"(d) : "f"(lo), "f"(hi));
    return d;
}
__device__ __forceinline__ float hsum2(ull v) {
    float lo, hi;
    asm("mov.b64 {%0, %1}, %2;" : "=f"(lo), "=f"(hi) : "l"(v));
    return lo + hi;
}

struct Chain { float hs, hx1, hx2, hx3, c; };

__global__ __launch_bounds__(BLOCK, 8) void lstm_kernel(
    const float* __restrict__ x,     // [B, T, I]
    const float* __restrict__ Wih,   // [16, 8]
    const float* __restrict__ Whh,   // [16, 4]
    const float* __restrict__ bih,   // [16]
    const float* __restrict__ bhh,   // [16]
    const float* __restrict__ fcw,   // [1, 4]
    const float* __restrict__ fcb,   // [1]
    float* __restrict__ out,         // [B, 1]
    int B)
{
    __shared__ float4 sm[2][EPB * STRIDE4];

    const int t = threadIdx.x;
    const int g = t >> 3;             // group 0..7 within block
    const int u = t & 7;              // lane within group
    const int k = u & 3;              // hidden unit
    const int p = u >> 2;             // 0: (i,f) rows, 1: (g,o) rows
    const int eA = 2 * g;             // local element of chain A
    const int eB = 2 * g + 1;         // local element of chain B
    const int bA = blockIdx.x * EPB + eA;
    const int bB = blockIdx.x * EPB + eB;

    // Rows owned by this thread (shared by both chains).
    const int rowA = p ? (8 + k)  : k;        // i or g
    const int rowB = p ? (12 + k) : (4 + k);  // f or o
    const float sA = p ? 1.0f : 0.5f;         // g uses tanh; i/f/o sigmoid 0.5-prescale
    const float actA_m = p ? 1.0f : 0.5f, actA_b = p ? 0.0f : 0.5f;

    ull wxA[4], wxB[4], whA[2], whB[2], biA, biB;
#pragma unroll
    for (int j = 0; j < 4; j++) {
        wxA[j] = pack2(sA   * Wih[rowA * I_DIM + 2 * j], sA   * Wih[rowA * I_DIM + 2 * j + 1]);
        wxB[j] = pack2(0.5f * Wih[rowB * I_DIM + 2 * j], 0.5f * Wih[rowB * I_DIM + 2 * j + 1]);
    }
    whA[0] = pack2(sA   * Whh[rowA * 4 + (k ^ 0)], sA   * Whh[rowA * 4 + (k ^ 1)]);
    whA[1] = pack2(sA   * Whh[rowA * 4 + (k ^ 2)], sA   * Whh[rowA * 4 + (k ^ 3)]);
    whB[0] = pack2(0.5f * Whh[rowB * 4 + (k ^ 0)], 0.5f * Whh[rowB * 4 + (k ^ 1)]);
    whB[1] = pack2(0.5f * Whh[rowB * 4 + (k ^ 2)], 0.5f * Whh[rowB * 4 + (k ^ 3)]);
    biA = pack2(sA   * (bih[rowA] + bhh[rowA]), 0.0f);
    biB = pack2(0.5f * (bih[rowB] + bhh[rowB]), 0.0f);

    Chain cA = {0.f, 0.f, 0.f, 0.f, 0.f};
    Chain cB = {0.f, 0.f, 0.f, 0.f, 0.f};
    const unsigned FULL = 0xffffffffu;

    auto STEP = [&](Chain& ch, ulonglong2 xlo, ulonglong2 xhi) {
        const ull h01 = pack2(ch.hs,  ch.hx1);
        const ull h23 = pack2(ch.hx2, ch.hx3);

        ull accA = ffma2(wxA[0], xlo.x, biA);
        accA = ffma2(wxA[1], xlo.y, accA);
        accA = ffma2(wxA[2], xhi.x, accA);
        accA = ffma2(wxA[3], xhi.y, accA);
        accA = ffma2(whA[0], h01, accA);
        accA = ffma2(whA[1], h23, accA);
        const float za = hsum2(accA);

        ull accB = ffma2(wxB[0], xlo.x, biB);
        accB = ffma2(wxB[1], xlo.y, accB);
        accB = ffma2(wxB[2], xhi.x, accB);
        accB = ffma2(wxB[3], xhi.y, accB);
        accB = ffma2(whB[0], h01, accB);
        accB = ffma2(whB[1], h23, accB);
        const float zb = hsum2(accB);

        // aa: p=0 -> sigmoid(i), p=1 -> tanh(g). ab: sigmoid (f or o).
        const float aa = fmaf(tanh_fast(za), actA_m, actA_b);
        const float ab = fmaf(tanh_fast(zb), 0.5f, 0.5f);

        // swap gate pairs between octet halves (parallel)
        const float e1 = __shfl_xor_sync(FULL, aa, 4);  // p0 gets g, p1 gets i
        const float e2 = __shfl_xor_sync(FULL, ab, 4);  // p0 gets o, p1 gets f

        const float fgate = p ? e2 : ab;
        const float ogate = p ? ab : e2;
        ch.c  = fmaf(fgate, ch.c, aa * e1);   // i*g == aa*e1 in both halves
        ch.hs = ogate * tanh_fast(ch.c);

        // h broadcast within the k-nibble (parallel butterflies)
        ch.hx1 = __shfl_xor_sync(FULL, ch.hs, 1);
        ch.hx2 = __shfl_xor_sync(FULL, ch.hs, 2);
        ch.hx3 = __shfl_xor_sync(FULL, ch.hs, 3);
    };

    // Staging map: 256 float4 per chunk (16 elem x 16 quads), 64 threads x 4 each.
    const float4* xf4 = reinterpret_cast<const float4*>(x);
    // float4 index f = e*16 + q ; thread handles f = t + 64*j, j=0..3
    float4 pf[4];

    // Prologue: stage chunk 0.
#pragma unroll
    for (int j = 0; j < 4; j++) {
        const int f = t + 64 * j;
        const int e = f >> 4, q = f & 15;
        const int be = blockIdx.x * EPB + e;
        sm[0][e * STRIDE4 + q] = xf4[(size_t)be * (T_STEPS * 2) + q];
    }
    __syncthreads();

    for (int ck = 0; ck < NCHUNK; ck++) {
        const bool more = (ck + 1 < NCHUNK);
        if (more) {
#pragma unroll
            for (int j = 0; j < 4; j++) {
                const int f = t + 64 * j;
                const int e = f >> 4, q = f & 15;
                const int be = blockIdx.x * EPB + e;
                pf[j] = xf4[(size_t)be * (T_STEPS * 2) + (ck + 1) * 16 + q];
            }
        }

        const float4* buf = sm[ck & 1];
        const ulonglong2* xA = reinterpret_cast<const ulonglong2*>(buf + eA * STRIDE4);
        const ulonglong2* xB = reinterpret_cast<const ulonglong2*>(buf + eB * STRIDE4);

#pragma unroll
        for (int s = 0; s < CH_STEPS; s++) {
            const ulonglong2 aLo = xA[2 * s], aHi = xA[2 * s + 1];
            const ulonglong2 bLo = xB[2 * s], bHi = xB[2 * s + 1];
            STEP(cA, aLo, aHi);
            STEP(cB, bLo, bHi);
        }

        if (more) {
#pragma unroll
            for (int j = 0; j < 4; j++) {
                const int f = t + 64 * j;
                const int e = f >> 4, q = f & 15;
                sm[(ck + 1) & 1][e * STRIDE4 + q] = pf[j];
            }
        }
        __syncthreads();
    }

    // ---- final FC: lane u==0 (k=0, p=0) holds h0..h3 for both chains ----
    if (u == 0) {
        out[bA] = fmaf(cA.hs, fcw[0], fmaf(cA.hx1, fcw[1], fmaf(cA.hx2, fcw[2], fmaf(cA.hx3, fcw[3], fcb[0]))));
        out[bB] = fmaf(cB.hs, fcw[0], fmaf(cB.hx1, fcw[1], fmaf(cB.hx2, fcw[2], fmaf(cB.hx3, fcw[3], fcb[0]))));
    }
}

extern "C" void kernel_launch(void* const* d_in, const int* in_sizes, int n_in,
                              void* d_out, int out_size)
{
    const float* x    = (const float*)d_in[0];
    const float* Wih  = (const float*)d_in[1];
    const float* Whh  = (const float*)d_in[2];
    const float* bih  = (const float*)d_in[3];
    const float* bhh  = (const float*)d_in[4];
    const float* fcw  = (const float*)d_in[5];
    const float* fcb  = (const float*)d_in[6];
    float* out = (float*)d_out;

    const int B = in_sizes[0] / (T_STEPS * I_DIM);   // 4096
    const int grid = B / EPB;                        // 256 blocks of 2 warps

    lstm_kernel<<<grid, BLOCK>>>(x, Wih, Whh, bih, bhh, fcw, fcb, out, B);
}